// round 1
// baseline (speedup 1.0000x reference)
#include <cuda_runtime.h>
#include <math.h>

#define SQ   2048
#define HDIM 2048
#define NH   16
#define NKV  8
#define HD   128
#define FF   8192

// ---------------- scratch (device globals; no allocs allowed) ----------------
__device__ float g_h1[SQ * HDIM];          // rmsnorm output (reused for both norms)
__device__ float g_q[SQ * NH * HD];
__device__ float g_k[SQ * NKV * HD];
__device__ float g_v[SQ * NKV * HD];
__device__ float g_attn[SQ * NH * HD];
__device__ float g_gate[1024 * FF];
__device__ float g_up[1024 * FF];

// ---------------- RMSNorm ----------------
__global__ void rmsnorm_kernel(const float* __restrict__ x, const float* __restrict__ w,
                               float* __restrict__ y, float* __restrict__ y2) {
    int row = blockIdx.x;
    const float* xr = x + (size_t)row * HDIM;
    float ss = 0.f;
    for (int i = threadIdx.x; i < HDIM; i += 256) { float v = xr[i]; ss = fmaf(v, v, ss); }
    for (int o = 16; o > 0; o >>= 1) ss += __shfl_xor_sync(0xffffffffu, ss, o);
    __shared__ float red[8];
    int wid = threadIdx.x >> 5, lane = threadIdx.x & 31;
    if (lane == 0) red[wid] = ss;
    __syncthreads();
    if (wid == 0) {
        float t = (lane < 8) ? red[lane] : 0.f;
        for (int o = 4; o > 0; o >>= 1) t += __shfl_xor_sync(0xffffffffu, t, o);
        if (lane == 0) red[0] = t;
    }
    __syncthreads();
    float scale = rsqrtf(red[0] / (float)HDIM + 1e-6f);
    for (int i = threadIdx.x; i < HDIM; i += 256) {
        float v = xr[i] * scale * w[i];
        y[(size_t)row * HDIM + i] = v;
        if (y2) y2[(size_t)row * HDIM + i] = v;
    }
}

// ---------------- RoPE (in-place on q and k) ----------------
__global__ void rope_kernel(float* __restrict__ q, float* __restrict__ k,
                            const float* __restrict__ cosb, const float* __restrict__ sinb) {
    int idx = blockIdx.x * blockDim.x + threadIdx.x;   // SQ * 24 * 64 total
    if (idx >= SQ * 24 * 64) return;
    int d  = idx & 63;
    int hh = (idx >> 6) % 24;
    int s  = idx / (24 * 64);
    float c1 = cosb[s * HD + d],      s1 = sinb[s * HD + d];
    float c2 = cosb[s * HD + d + 64], s2 = sinb[s * HD + d + 64];
    float* base;
    if (hh < NH) base = q + (size_t)s * (NH * HD) + hh * HD;
    else         base = k + (size_t)s * (NKV * HD) + (hh - NH) * HD;
    float a = base[d], b = base[d + 64];
    base[d]      = a * c1 - b * s1;
    base[d + 64] = b * c2 + a * s2;
}

// ---------------- SGEMM 128x128x8, 256 threads, 8x8 microtile ----------------
// C[M,N] = gather_A(arow) @ B (+ cadd), scatter rows with crow.
__global__ void __launch_bounds__(256) sgemm_kernel(
    const float* __restrict__ A, const float* __restrict__ B, float* __restrict__ C,
    int M, int N, int K,
    const int* __restrict__ arow, const int* __restrict__ crow,
    const float* __restrict__ cadd)
{
    __shared__ float As[8][128];
    __shared__ float Bs[8][128];
    const int tid = threadIdx.x;
    const int m0 = blockIdx.y * 128, n0 = blockIdx.x * 128;
    const int lam = tid >> 1, lak = (tid & 1) << 2;
    const int lbk = tid >> 5, lbn = (tid & 31) << 2;
    int am = m0 + lam;
    if (arow) am = arow[am];
    const float* Ap = A + (size_t)am * K + lak;
    const float* Bp = B + (size_t)lbk * K == 0 ? B : B; // (no-op; keep compiler calm)
    Bp = B + (size_t)lbk * N + n0 + lbn;
    const int tx = tid & 15, ty = tid >> 4;
    float acc[8][8];
#pragma unroll
    for (int i = 0; i < 8; i++)
#pragma unroll
        for (int j = 0; j < 8; j++) acc[i][j] = 0.f;

    for (int k0 = 0; k0 < K; k0 += 8) {
        float4 a4 = *(const float4*)(Ap + k0);
        float4 b4 = *(const float4*)(Bp + (size_t)k0 * N);
        __syncthreads();
        As[lak + 0][lam] = a4.x;
        As[lak + 1][lam] = a4.y;
        As[lak + 2][lam] = a4.z;
        As[lak + 3][lam] = a4.w;
        *(float4*)&Bs[lbk][lbn] = b4;
        __syncthreads();
#pragma unroll
        for (int kk = 0; kk < 8; kk++) {
            float ra[8], rb[8];
            *(float4*)&ra[0] = *(const float4*)&As[kk][ty * 8];
            *(float4*)&ra[4] = *(const float4*)&As[kk][ty * 8 + 4];
            *(float4*)&rb[0] = *(const float4*)&Bs[kk][tx * 8];
            *(float4*)&rb[4] = *(const float4*)&Bs[kk][tx * 8 + 4];
#pragma unroll
            for (int i = 0; i < 8; i++)
#pragma unroll
                for (int j = 0; j < 8; j++)
                    acc[i][j] = fmaf(ra[i], rb[j], acc[i][j]);
        }
    }
#pragma unroll
    for (int i = 0; i < 8; i++) {
        int row = m0 + ty * 8 + i;
        int orow = crow ? crow[row] : row;
        float* Cp = C + (size_t)orow * N + n0 + tx * 8;
        if (cadd) {
            const float* ap = cadd + (size_t)row * N + n0 + tx * 8;
#pragma unroll
            for (int j = 0; j < 8; j++) Cp[j] = acc[i][j] + ap[j];
        } else {
#pragma unroll
            for (int j = 0; j < 8; j++) Cp[j] = acc[i][j];
        }
    }
}

// ---------------- Flash attention (causal, GQA rep=2), fp32 ----------------
// BM=BN=64, 256 threads: thread = (row r = tid>>2, quarter qd = tid&3).
// acc dim mapping: d = qd + 4*i (conflict-free Vs reads).
#define FLASH_SMEM ((3 * 64 * 129 + 64 * 65) * 4)

__global__ void __launch_bounds__(256) flash_kernel(
    const float* __restrict__ q, const float* __restrict__ k,
    const float* __restrict__ v, float* __restrict__ o)
{
    extern __shared__ float sm[];
    float* Qs = sm;                 // 64*129
    float* Ks = Qs + 64 * 129;
    float* Vs = Ks + 64 * 129;
    float* Ps = Vs + 64 * 129;      // 64*65
    const int h = blockIdx.y;
    const int qt = blockIdx.x;
    const int kh = h >> 1;
    const int tid = threadIdx.x;
    const int r = tid >> 2, qd = tid & 3;
    const float scale = 0.08838834764831845f;  // 1/sqrt(128)

    {
        const float* qp = q + (size_t)(qt * 64 + r) * (NH * HD) + h * HD + qd * 32;
#pragma unroll
        for (int j = 0; j < 32; j += 4) {
            float4 t = *(const float4*)(qp + j);
            float* d = &Qs[r * 129 + qd * 32 + j];
            d[0] = t.x; d[1] = t.y; d[2] = t.z; d[3] = t.w;
        }
    }
    float m_i = -1e30f, l_i = 0.f;
    float acc[32];
#pragma unroll
    for (int i = 0; i < 32; i++) acc[i] = 0.f;

    for (int kb = 0; kb <= qt; kb++) {
        __syncthreads();
        {
            const float* kp = k + (size_t)(kb * 64 + r) * (NKV * HD) + kh * HD + qd * 32;
            const float* vp = v + (size_t)(kb * 64 + r) * (NKV * HD) + kh * HD + qd * 32;
#pragma unroll
            for (int j = 0; j < 32; j += 4) {
                float4 tk = *(const float4*)(kp + j);
                float4 tv = *(const float4*)(vp + j);
                float* dk = &Ks[r * 129 + qd * 32 + j];
                dk[0] = tk.x; dk[1] = tk.y; dk[2] = tk.z; dk[3] = tk.w;
                float* dv = &Vs[r * 129 + qd * 32 + j];
                dv[0] = tv.x; dv[1] = tv.y; dv[2] = tv.z; dv[3] = tv.w;
            }
        }
        __syncthreads();
        float sc[16];
#pragma unroll
        for (int c = 0; c < 16; c++) sc[c] = 0.f;
        for (int t = 0; t < 128; t++) {
            float qv = Qs[r * 129 + t];
#pragma unroll
            for (int c = 0; c < 16; c++)
                sc[c] = fmaf(qv, Ks[(qd * 16 + c) * 129 + t], sc[c]);
        }
        const int gi = qt * 64 + r;
        float mrow = -1e30f;
#pragma unroll
        for (int c = 0; c < 16; c++) {
            int gj = kb * 64 + qd * 16 + c;
            sc[c] = (gj <= gi) ? sc[c] * scale : -1e30f;
            mrow = fmaxf(mrow, sc[c]);
        }
        mrow = fmaxf(mrow, __shfl_xor_sync(0xffffffffu, mrow, 1));
        mrow = fmaxf(mrow, __shfl_xor_sync(0xffffffffu, mrow, 2));
        float m_new = fmaxf(m_i, mrow);
        float alpha = __expf(m_i - m_new);
        float psum = 0.f;
#pragma unroll
        for (int c = 0; c < 16; c++) {
            float p = __expf(sc[c] - m_new);
            Ps[r * 65 + qd * 16 + c] = p;
            psum += p;
        }
        psum += __shfl_xor_sync(0xffffffffu, psum, 1);
        psum += __shfl_xor_sync(0xffffffffu, psum, 2);
        l_i = l_i * alpha + psum;
        m_i = m_new;
#pragma unroll
        for (int i = 0; i < 32; i++) acc[i] *= alpha;
        __syncthreads();
        for (int c = 0; c < 64; c++) {
            float pv = Ps[r * 65 + c];
#pragma unroll
            for (int i = 0; i < 32; i++)
                acc[i] = fmaf(pv, Vs[c * 129 + qd + 4 * i], acc[i]);
        }
    }
    float inv = 1.f / l_i;
    float* op = o + (size_t)(qt * 64 + r) * (NH * HD) + h * HD + qd;
#pragma unroll
    for (int i = 0; i < 32; i++) op[4 * i] = acc[i] * inv;
}

// ---------------- SiLU(gate) * up, in-place into gate ----------------
__global__ void silu_mul_kernel(float* __restrict__ g, const float* __restrict__ u, int n4) {
    int i = blockIdx.x * blockDim.x + threadIdx.x;
    if (i >= n4) return;
    float4 a = ((const float4*)g)[i];
    float4 b = ((const float4*)u)[i];
    a.x = a.x / (1.f + __expf(-a.x)) * b.x;
    a.y = a.y / (1.f + __expf(-a.y)) * b.y;
    a.z = a.z / (1.f + __expf(-a.z)) * b.z;
    a.w = a.w / (1.f + __expf(-a.w)) * b.w;
    ((float4*)g)[i] = a;
}

// ---------------- launch ----------------
extern "C" void kernel_launch(void* const* d_in, const int* in_sizes, int n_in,
                              void* d_out, int out_size) {
    const float* x    = (const float*)d_in[0];
    const float* cosb = (const float*)d_in[1];
    const float* sinb = (const float*)d_in[2];
    const float* wq   = (const float*)d_in[3];
    const float* wk   = (const float*)d_in[4];
    const float* wv   = (const float*)d_in[5];
    const float* wo   = (const float*)d_in[6];
    const float* w1   = (const float*)d_in[7];
    const float* w3   = (const float*)d_in[8];
    const float* w2   = (const float*)d_in[9];
    const float* v1   = (const float*)d_in[10];
    const float* v3   = (const float*)d_in[11];
    const float* v2   = (const float*)d_in[12];
    const float* anw  = (const float*)d_in[13];
    const float* fnw  = (const float*)d_in[14];
    const int*   vis  = (const int*)d_in[15];
    const int*   txt  = (const int*)d_in[16];

    float* out = (float*)d_out;                 // [SQ*HDIM] final hidden
    float* res = out + (size_t)SQ * HDIM;       // [SQ*HDIM] residual

    float *h1, *qb, *kb_, *vb, *ab, *gb, *ub;
    cudaGetSymbolAddress((void**)&h1, g_h1);
    cudaGetSymbolAddress((void**)&qb, g_q);
    cudaGetSymbolAddress((void**)&kb_, g_k);
    cudaGetSymbolAddress((void**)&vb, g_v);
    cudaGetSymbolAddress((void**)&ab, g_attn);
    cudaGetSymbolAddress((void**)&gb, g_gate);
    cudaGetSymbolAddress((void**)&ub, g_up);

    cudaFuncSetAttribute(flash_kernel, cudaFuncAttributeMaxDynamicSharedMemorySize, FLASH_SMEM);

    // 1) attn rmsnorm
    rmsnorm_kernel<<<SQ, 256>>>(x, anw, h1, nullptr);
    // 2) QKV projections
    sgemm_kernel<<<dim3(HDIM / 128, SQ / 128), 256>>>(h1, wq, qb, SQ, HDIM, HDIM, nullptr, nullptr, nullptr);
    sgemm_kernel<<<dim3((NKV * HD) / 128, SQ / 128), 256>>>(h1, wk, kb_, SQ, NKV * HD, HDIM, nullptr, nullptr, nullptr);
    sgemm_kernel<<<dim3((NKV * HD) / 128, SQ / 128), 256>>>(h1, wv, vb, SQ, NKV * HD, HDIM, nullptr, nullptr, nullptr);
    // 3) RoPE
    {
        int n = SQ * 24 * 64;
        rope_kernel<<<(n + 255) / 256, 256>>>(qb, kb_, cosb, sinb);
    }
    // 4) attention
    flash_kernel<<<dim3(SQ / 64, NH), 256, FLASH_SMEM>>>(qb, kb_, vb, ab);
    // 5) o-proj + residual -> res
    sgemm_kernel<<<dim3(HDIM / 128, SQ / 128), 256>>>(ab, wo, res, SQ, HDIM, HDIM, nullptr, nullptr, x);
    // 6) ffn rmsnorm -> h1 (and baseline copy into out)
    rmsnorm_kernel<<<SQ, 256>>>(res, fnw, h1, out);
    // 7) vision MLP (gather rows via vis, scatter back into out)
    sgemm_kernel<<<dim3(FF / 128, 1024 / 128), 256>>>(h1, v1, gb, 1024, FF, HDIM, vis, nullptr, nullptr);
    sgemm_kernel<<<dim3(FF / 128, 1024 / 128), 256>>>(h1, v3, ub, 1024, FF, HDIM, vis, nullptr, nullptr);
    silu_mul_kernel<<<(1024 * FF / 4 + 255) / 256, 256>>>(gb, ub, 1024 * FF / 4);
    sgemm_kernel<<<dim3(HDIM / 128, 1024 / 128), 256>>>(gb, v2, out, 1024, HDIM, FF, nullptr, vis, nullptr);
    // 8) text MLP
    sgemm_kernel<<<dim3(FF / 128, 1024 / 128), 256>>>(h1, w1, gb, 1024, FF, HDIM, txt, nullptr, nullptr);
    sgemm_kernel<<<dim3(FF / 128, 1024 / 128), 256>>>(h1, w3, ub, 1024, FF, HDIM, txt, nullptr, nullptr);
    silu_mul_kernel<<<(1024 * FF / 4 + 255) / 256, 256>>>(gb, ub, 1024 * FF / 4);
    sgemm_kernel<<<dim3(HDIM / 128, 1024 / 128), 256>>>(gb, w2, out, 1024, HDIM, FF, nullptr, txt, nullptr);
}